// round 3
// baseline (speedup 1.0000x reference)
#include <cuda_runtime.h>
#include <math.h>

// Problem constants
#define NB    16
#define NDIM  256
#define SS    64
#define NHEADS 4
#define HD    16
#define NPIX  4096
#define NBB   64

// ---------------- scratch ----------
__device__ float g_y[(size_t)NB * NDIM * NPIX];
__device__ float g_qkv[(size_t)NBB * 192 * NPIX];
__device__ float g_M[4096];
__device__ float g_Z[4096];
__device__ float g_ctx[(size_t)NBB * NHEADS * HD * HD];
__device__ float g_ao[(size_t)NBB * SS * NPIX];
__device__ float g_cat[(size_t)NB * NDIM * NPIX];

// ---------------- f32x2 helpers -------------------------------------------
__device__ __forceinline__ void ffma2(unsigned long long& d,
                                      unsigned long long a,
                                      unsigned long long b) {
    asm("fma.rn.f32x2 %0, %1, %2, %0;" : "+l"(d) : "l"(a), "l"(b));
}
__device__ __forceinline__ unsigned long long dup2(float x) {
    unsigned long long r;
    asm("mov.b64 %0, {%1, %1};" : "=l"(r) : "f"(x));
    return r;
}
__device__ __forceinline__ float2 unpack2(unsigned long long v) {
    float2 r;
    asm("mov.b64 {%0, %1}, %2;" : "=f"(r.x), "=f"(r.y) : "l"(v));
    return r;
}

// ---------------- depthwise conv + bias + residual + relu -----------------
__global__ __launch_bounds__(256) void dwconv_kernel(
    const float* __restrict__ x,
    const float* __restrict__ w3, const float* __restrict__ b3,
    const float* __restrict__ w5, const float* __restrict__ b5,
    const float* __restrict__ w7, const float* __restrict__ b7,
    const float* __restrict__ w9, const float* __restrict__ b9)
{
    __shared__ float s[4096];
    __shared__ float ws[81];
    int bc = blockIdx.x;
    int cg = bc & 255;
    int br = cg >> 6;
    int c  = cg & 63;
    const float* wsrc; const float* bsrc; int k;
    if (br == 0)      { wsrc = w3; bsrc = b3; k = 3; }
    else if (br == 1) { wsrc = w5; bsrc = b5; k = 5; }
    else if (br == 2) { wsrc = w7; bsrc = b7; k = 7; }
    else              { wsrc = w9; bsrc = b9; k = 9; }
    int t = threadIdx.x;
    const float* xp = x + (size_t)bc * NPIX;
    #pragma unroll
    for (int i = 0; i < 16; i++) s[t + i * 256] = xp[t + i * 256];
    if (t < k * k) ws[t] = wsrc[c * k * k + t];
    float bv = bsrc[c];
    __syncthreads();
    int r = k >> 1;
    for (int i = 0; i < 16; i++) {
        int p  = t + i * 256;
        int py = p >> 6, px = p & 63;
        float acc = 0.f;
        for (int u = 0; u < k; u++) {
            int yy = py + u - r;
            if ((unsigned)yy >= 64u) continue;
            const float* srow = &s[yy * 64];
            const float* wrow = &ws[u * k];
            for (int v = 0; v < k; v++) {
                int xx = px + v - r;
                if ((unsigned)xx >= 64u) continue;
                acc += srow[xx] * wrow[v];
            }
        }
        float o = acc + bv + s[p];
        g_y[(size_t)bc * NPIX + p] = fmaxf(o, 0.f);
    }
}

// ---------------- f32x2-packed GEMM: C(m,j) = A(m,k) * W(j,k) -------------
// A/C layout: elem(m,k) = base[chunk*stride + k*4096 + (m&4095)], 4096-row chunks.
// CTA tile: 256(m) x 64(j), K-step 16, 256 threads, 16m x 4j micro-tile.
// Accumulators are f32x2 packed along m.
__global__ __launch_bounds__(256, 2) void gemm_f2(
    const float* __restrict__ A, const float* __restrict__ W,
    const float* __restrict__ bias, const float* __restrict__ scalew,
    float* __restrict__ C, int K, long chunkA, long chunkC)
{
    __shared__ __align__(16) float As[16][256];   // 16 KB
    __shared__ __align__(16) float Bs[16][64];    // 4 KB

    int m0    = blockIdx.x * 256;
    int chunk = m0 >> 12;
    int mloc  = m0 & 4095;
    int j0    = blockIdx.y * 64;

    const float* Ab = A + (size_t)chunk * chunkA + mloc;
    const float* Wb = W + (size_t)j0 * K;
    float*       Cb = C + (size_t)chunk * chunkC + mloc + (size_t)j0 * 4096;
    float scale = scalew ? scalew[chunk & 3] : 1.0f;

    int tid = threadIdx.x;
    int tm = tid & 15;          // m group
    int tj = tid >> 4;          // j group (0..15) -> j0loc = tj*4

    // global-load indices
    int ka = tid >> 6;          // 0..3
    int ma = (tid & 63) * 4;    // 0..252
    int jb = tid & 63;          // 0..63
    int kb = (tid >> 6) * 4;    // 0,4,8,12

    unsigned long long acc[4][2][4];
    #pragma unroll
    for (int s = 0; s < 4; s++)
        #pragma unroll
        for (int p = 0; p < 2; p++)
            #pragma unroll
            for (int j = 0; j < 4; j++) acc[s][p][j] = 0ULL;

    for (int k0 = 0; k0 < K; k0 += 16) {
        // fill As: 16 floats per thread
        #pragma unroll
        for (int r = 0; r < 4; r++) {
            int kk = r * 4 + ka;
            *(float4*)&As[kk][ma] = *(const float4*)(Ab + (size_t)(k0 + kk) * 4096 + ma);
        }
        // fill Bs: 4 floats per thread (transpose k-major W row into Bs[k][j])
        {
            float4 wv = *(const float4*)(Wb + (size_t)jb * K + k0 + kb);
            Bs[kb + 0][jb] = wv.x;
            Bs[kb + 1][jb] = wv.y;
            Bs[kb + 2][jb] = wv.z;
            Bs[kb + 3][jb] = wv.w;
        }
        __syncthreads();

        #pragma unroll
        for (int kk = 0; kk < 16; kk++) {
            float4 b4 = *(const float4*)&Bs[kk][tj * 4];
            unsigned long long bb[4];
            bb[0] = dup2(b4.x); bb[1] = dup2(b4.y);
            bb[2] = dup2(b4.z); bb[3] = dup2(b4.w);
            #pragma unroll
            for (int s = 0; s < 4; s++) {
                ulonglong2 av = *(const ulonglong2*)&As[kk][s * 64 + tm * 4];
                #pragma unroll
                for (int j = 0; j < 4; j++) {
                    ffma2(acc[s][0][j], av.x, bb[j]);
                    ffma2(acc[s][1][j], av.y, bb[j]);
                }
            }
        }
        __syncthreads();
    }

    // epilogue: (acc + bias) * scale, store float4 along m
    #pragma unroll
    for (int j = 0; j < 4; j++) {
        int jg = tj * 4 + j;
        float bj = bias ? bias[j0 + jg] : 0.f;
        #pragma unroll
        for (int s = 0; s < 4; s++) {
            float2 lo = unpack2(acc[s][0][j]);
            float2 hi = unpack2(acc[s][1][j]);
            float4 o;
            o.x = (lo.x + bj) * scale;
            o.y = (lo.y + bj) * scale;
            o.z = (hi.x + bj) * scale;
            o.w = (hi.y + bj) * scale;
            *(float4*)(Cb + (size_t)jg * 4096 + s * 64 + tm * 4) = o;
        }
    }
}

// ---------------- softmax over hd=16 on K (in place) ----------------------
__global__ __launch_bounds__(256) void ksoftmax_kernel()
{
    int idx = blockIdx.x * 256 + threadIdx.x;
    int n  = idx & 4095;
    int hh = idx >> 12;
    int bb = hh >> 2, h = hh & 3;
    float* base = g_qkv + ((size_t)(bb * 192 + 64 + h * 16)) * 4096 + n;
    float v[16];
    float mx = -3.4e38f;
    #pragma unroll
    for (int d = 0; d < 16; d++) { v[d] = base[(size_t)d * 4096]; mx = fmaxf(mx, v[d]); }
    float ssum = 0.f;
    #pragma unroll
    for (int d = 0; d < 16; d++) { v[d] = __expf(v[d] - mx); ssum += v[d]; }
    float inv = 1.0f / ssum;
    #pragma unroll
    for (int d = 0; d < 16; d++) base[(size_t)d * 4096] = v[d] * inv;
}

// ---------------- column stats (max, sumexp) over n for Q -----------------
__global__ __launch_bounds__(256) void qstats_kernel()
{
    __shared__ float red[256];
    int col = blockIdx.x;
    int bb = col >> 6, j = col & 63;
    const float* base = g_qkv + ((size_t)(bb * 192 + j)) * 4096;
    int t = threadIdx.x;
    float v[16];
    float mx = -3.4e38f;
    #pragma unroll
    for (int i = 0; i < 16; i++) { v[i] = base[t + i * 256]; mx = fmaxf(mx, v[i]); }
    red[t] = mx; __syncthreads();
    for (int s2 = 128; s2 > 0; s2 >>= 1) {
        if (t < s2) red[t] = fmaxf(red[t], red[t + s2]);
        __syncthreads();
    }
    mx = red[0]; __syncthreads();
    float sum = 0.f;
    #pragma unroll
    for (int i = 0; i < 16; i++) sum += __expf(v[i] - mx);
    red[t] = sum; __syncthreads();
    for (int s2 = 128; s2 > 0; s2 >>= 1) {
        if (t < s2) red[t] += red[t + s2];
        __syncthreads();
    }
    if (t == 0) { g_M[col] = mx; g_Z[col] = red[0]; }
}

// ---------------- context: C[d,e] = sum_n key[n,d] v[n,e], / Z ------------
__global__ __launch_bounds__(256) void context_kernel()
{
    __shared__ float ks[16][128];
    __shared__ float vs[16][128];
    int bh = blockIdx.x;
    int bb = bh >> 2, h = bh & 3;
    const float* kb = g_qkv + ((size_t)(bb * 192 + 64  + h * 16)) * 4096;
    const float* vb = g_qkv + ((size_t)(bb * 192 + 128 + h * 16)) * 4096;
    int t = threadIdx.x;
    int d = t >> 4, e = t & 15;
    float acc = 0.f;
    for (int n0 = 0; n0 < 4096; n0 += 128) {
        #pragma unroll
        for (int i = 0; i < 2; i++) {
            int idx = t * 2 + i;
            int row = idx >> 5;
            int c4  = (idx & 31) * 4;
            *(float4*)&ks[row][c4] = *(const float4*)(kb + (size_t)row * 4096 + n0 + c4);
            *(float4*)&vs[row][c4] = *(const float4*)(vb + (size_t)row * 4096 + n0 + c4);
        }
        __syncthreads();
        #pragma unroll
        for (int q4 = 0; q4 < 32; q4++) {
            float4 a = *(const float4*)&ks[d][q4 * 4];
            float4 b = *(const float4*)&vs[e][q4 * 4];
            acc += a.x * b.x + a.y * b.y + a.z * b.z + a.w * b.w;
        }
        __syncthreads();
    }
    float z = g_Z[bb * 64 + h * 16 + d];
    g_ctx[(size_t)bh * 256 + d * 16 + e] = acc / z;
}

// ---------------- attn out: ao = exp(q-M) @ ctx, reference reshape folded:
//   pixel  n' = h*1024 + (n>>2),  chan c' = 16*(n&3) + e
__global__ __launch_bounds__(256) void attnout_kernel()
{
    __shared__ float cs[1024];
    __shared__ float ms[64];
    int bb = blockIdx.x >> 4;
    int nt = blockIdx.x & 15;
    int t  = threadIdx.x;
    int n  = nt * 256 + t;
    if (t < 64) ms[t] = g_M[bb * 64 + t];
    for (int i = t; i < 1024; i += 256) cs[i] = g_ctx[(size_t)bb * 1024 + i];
    __syncthreads();
    const float* qb = g_qkv + (size_t)bb * 192 * 4096 + n;
    int cbase = 16 * (n & 3);
    int pbase = n >> 2;
    for (int h = 0; h < 4; h++) {
        float acc[16];
        #pragma unroll
        for (int e = 0; e < 16; e++) acc[e] = 0.f;
        #pragma unroll
        for (int d = 0; d < 16; d++) {
            int jc = h * 16 + d;
            float qv = __expf(qb[(size_t)jc * 4096] - ms[jc]);
            const float4* crow = (const float4*)&cs[jc * 16];
            #pragma unroll
            for (int e4 = 0; e4 < 4; e4++) {
                float4 cv = crow[e4];
                acc[e4 * 4 + 0] += qv * cv.x;
                acc[e4 * 4 + 1] += qv * cv.y;
                acc[e4 * 4 + 2] += qv * cv.z;
                acc[e4 * 4 + 3] += qv * cv.w;
            }
        }
        int np = h * 1024 + pbase;
        #pragma unroll
        for (int e = 0; e < 16; e++)
            g_ao[((size_t)(bb * 64 + cbase + e)) * 4096 + np] = acc[e];
    }
}

// ---------------- launch ---------------------------------------------------
extern "C" void kernel_launch(void* const* d_in, const int* in_sizes, int n_in,
                              void* d_out, int out_size)
{
    const float* x   = (const float*)d_in[0];
    const float* w3  = (const float*)d_in[1];
    const float* b3  = (const float*)d_in[2];
    const float* w5  = (const float*)d_in[3];
    const float* b5  = (const float*)d_in[4];
    const float* w7  = (const float*)d_in[5];
    const float* b7  = (const float*)d_in[6];
    const float* w9  = (const float*)d_in[7];
    const float* b9  = (const float*)d_in[8];
    const float* w_qkv   = (const float*)d_in[9];
    const float* w_proj  = (const float*)d_in[10];
    const float* b_proj  = (const float*)d_in[11];
    const float* w_final = (const float*)d_in[12];
    const float* b_final = (const float*)d_in[13];
    const float* scale_w = (const float*)d_in[14];
    float* out = (float*)d_out;

    float *yp, *qkvp, *aop, *catp;
    cudaGetSymbolAddress((void**)&yp,   g_y);
    cudaGetSymbolAddress((void**)&qkvp, g_qkv);
    cudaGetSymbolAddress((void**)&aop,  g_ao);
    cudaGetSymbolAddress((void**)&catp, g_cat);

    // 1. depthwise conv + bias + residual + relu  -> g_y (bb,c,n)
    dwconv_kernel<<<NB * NDIM, 256>>>(x, w3, b3, w5, b5, w7, b7, w9, b9);

    // 2. QKV GEMM: (262144 x 64) @ (192 x 64)^T -> g_qkv
    gemm_f2<<<dim3(262144 / 256, 3), 256>>>(yp, w_qkv, nullptr, nullptr, qkvp,
                                            64, 64L * 4096, 192L * 4096);

    // 3. softmax over hd for K (in place)
    ksoftmax_kernel<<<4096, 256>>>();

    // 4. column stats for Q softmax (axis = n)
    qstats_kernel<<<4096, 256>>>();

    // 5. context = key^T v, folded / Z
    context_kernel<<<256, 256>>>();

    // 6. attention out -> g_ao (scrambled reshape layout)
    attnout_kernel<<<1024, 256>>>();

    // 7. proj GEMM + bias + branch scale -> g_cat
    gemm_f2<<<dim3(262144 / 256, 1), 256>>>(aop, w_proj, b_proj, scale_w, catp,
                                            64, 64L * 4096, 64L * 4096);

    // 8. final 1x1 conv -> d_out
    gemm_f2<<<dim3(65536 / 256, 4), 256>>>(catp, w_final, b_final, nullptr, out,
                                           256, 256L * 4096, 256L * 4096);
}

// round 4
// speedup vs baseline: 1.8865x; 1.8865x over previous
#include <cuda_runtime.h>
#include <cuda_fp16.h>
#include <math.h>

// Problem constants
#define NB    16
#define NDIM  256
#define SS    64
#define NHEADS 4
#define HD    16
#define NPIX  4096
#define NBB   64

// ---------------- scratch ----------
__device__ float g_y[(size_t)NB * NDIM * NPIX];
__device__ float g_qkv[(size_t)NBB * 192 * NPIX];
__device__ float g_M[4096];
__device__ float g_Z[4096];
__device__ float g_ctx[(size_t)NBB * NHEADS * HD * HD];
__device__ float g_ao[(size_t)NBB * SS * NPIX];
__device__ float g_cat[(size_t)NB * NDIM * NPIX];

// ---------------- helpers ----------
__device__ __forceinline__ unsigned pack_h2(__half a, __half b) {
    return (unsigned)__half_as_ushort(a) | ((unsigned)__half_as_ushort(b) << 16);
}

__device__ __forceinline__ void mma16816(float* d, const unsigned* a, const unsigned* b) {
    asm volatile(
        "mma.sync.aligned.m16n8k16.row.col.f32.f16.f16.f32 "
        "{%0,%1,%2,%3}, {%4,%5,%6,%7}, {%8,%9}, {%0,%1,%2,%3};"
        : "+f"(d[0]), "+f"(d[1]), "+f"(d[2]), "+f"(d[3])
        : "r"(a[0]), "r"(a[1]), "r"(a[2]), "r"(a[3]), "r"(b[0]), "r"(b[1]));
}

// ---------------- depthwise conv + bias + residual + relu -----------------
__global__ __launch_bounds__(256) void dwconv_kernel(
    const float* __restrict__ x,
    const float* __restrict__ w3, const float* __restrict__ b3,
    const float* __restrict__ w5, const float* __restrict__ b5,
    const float* __restrict__ w7, const float* __restrict__ b7,
    const float* __restrict__ w9, const float* __restrict__ b9)
{
    __shared__ float s[4096];
    __shared__ float ws[81];
    int bc = blockIdx.x;
    int cg = bc & 255;
    int br = cg >> 6;
    int c  = cg & 63;
    const float* wsrc; const float* bsrc; int k;
    if (br == 0)      { wsrc = w3; bsrc = b3; k = 3; }
    else if (br == 1) { wsrc = w5; bsrc = b5; k = 5; }
    else if (br == 2) { wsrc = w7; bsrc = b7; k = 7; }
    else              { wsrc = w9; bsrc = b9; k = 9; }
    int t = threadIdx.x;
    const float* xp = x + (size_t)bc * NPIX;
    #pragma unroll
    for (int i = 0; i < 16; i++) s[t + i * 256] = xp[t + i * 256];
    if (t < k * k) ws[t] = wsrc[c * k * k + t];
    float bv = bsrc[c];
    __syncthreads();
    int r = k >> 1;
    for (int i = 0; i < 16; i++) {
        int p  = t + i * 256;
        int py = p >> 6, px = p & 63;
        float acc = 0.f;
        for (int u = 0; u < k; u++) {
            int yy = py + u - r;
            if ((unsigned)yy >= 64u) continue;
            const float* srow = &s[yy * 64];
            const float* wrow = &ws[u * k];
            for (int v = 0; v < k; v++) {
                int xx = px + v - r;
                if ((unsigned)xx >= 64u) continue;
                acc += srow[xx] * wrow[v];
            }
        }
        float o = acc + bv + s[p];
        g_y[(size_t)bc * NPIX + p] = fmaxf(o, 0.f);
    }
}

// ---------------- tensor-core GEMM with fp16 hi/lo split ------------------
// C(m,j) = sum_k A(m,k) * W(j,k);  A: [chunk][k*4096 + m], W: [j*K + k]
// CTA tile 128(m) x 64(j), K-step 32, 256 threads = 8 warps (4 m x 2 j).
// Each input split hi/lo fp16; 3 MMAs (AhBh + AhBl + AlBh), fp32 accum.
#define SAH 40   // smem row stride in halves
__global__ __launch_bounds__(256) void gemm_tc(
    const float* __restrict__ A, const float* __restrict__ W,
    const float* __restrict__ bias, const float* __restrict__ scalew,
    float* __restrict__ C, int K, long chunkA, long chunkC)
{
    __shared__ __align__(16) __half Ah[128][SAH];
    __shared__ __align__(16) __half Al[128][SAH];
    __shared__ __align__(16) __half Wh[64][SAH];
    __shared__ __align__(16) __half Wl[64][SAH];

    int m0    = blockIdx.x * 128;
    int chunk = m0 >> 12;
    int mloc  = m0 & 4095;
    int j0    = blockIdx.y * 64;

    const float* Ab = A + (size_t)chunk * chunkA + mloc;
    const float* Wb = W + (size_t)j0 * K;
    float*       Cb = C + (size_t)chunk * chunkC + mloc + (size_t)j0 * 4096;
    float scale = scalew ? scalew[chunk & 3] : 1.0f;

    int tid  = threadIdx.x;
    int wp   = tid >> 5;
    int lane = tid & 31;
    int g = lane >> 2, t4 = lane & 3;
    int warpm = wp & 3;         // 0..3 -> m offset 32*warpm
    int warpj = wp >> 2;        // 0..1 -> j offset 32*warpj

    // W-fill indices
    int jf = tid >> 2;          // 0..63
    int kf = (tid & 3) * 8;     // 0,8,16,24

    float acc[2][4][4];
    #pragma unroll
    for (int mi = 0; mi < 2; mi++)
        #pragma unroll
        for (int ji = 0; ji < 4; ji++)
            #pragma unroll
            for (int cc = 0; cc < 4; cc++) acc[mi][ji][cc] = 0.f;

    for (int k0 = 0; k0 < K; k0 += 32) {
        // ---- fill W (hi/lo) ----
        {
            float4 w0 = *(const float4*)(Wb + (size_t)jf * K + k0 + kf);
            float4 w1 = *(const float4*)(Wb + (size_t)jf * K + k0 + kf + 4);
            float v[8] = {w0.x, w0.y, w0.z, w0.w, w1.x, w1.y, w1.z, w1.w};
            __half hh[8], hl[8];
            #pragma unroll
            for (int i = 0; i < 8; i++) {
                hh[i] = __float2half_rn(v[i]);
                hl[i] = __float2half_rn(v[i] - __half2float(hh[i]));
            }
            uint4 uh, ul;
            uh.x = pack_h2(hh[0], hh[1]); uh.y = pack_h2(hh[2], hh[3]);
            uh.z = pack_h2(hh[4], hh[5]); uh.w = pack_h2(hh[6], hh[7]);
            ul.x = pack_h2(hl[0], hl[1]); ul.y = pack_h2(hl[2], hl[3]);
            ul.z = pack_h2(hl[4], hl[5]); ul.w = pack_h2(hl[6], hl[7]);
            *(uint4*)&Wh[jf][kf] = uh;
            *(uint4*)&Wl[jf][kf] = ul;
        }
        // ---- fill A (hi/lo), transposing k-major -> [m][k] ----
        {
            int kb = wp * 4;
            #pragma unroll
            for (int c = 0; c < 4; c++) {
                int m = c * 32 + lane;
                float v[4];
                #pragma unroll
                for (int i = 0; i < 4; i++)
                    v[i] = Ab[(size_t)(k0 + kb + i) * 4096 + m];
                __half hh[4], hl[4];
                #pragma unroll
                for (int i = 0; i < 4; i++) {
                    hh[i] = __float2half_rn(v[i]);
                    hl[i] = __float2half_rn(v[i] - __half2float(hh[i]));
                }
                uint2 uh, ul;
                uh.x = pack_h2(hh[0], hh[1]); uh.y = pack_h2(hh[2], hh[3]);
                ul.x = pack_h2(hl[0], hl[1]); ul.y = pack_h2(hl[2], hl[3]);
                *(uint2*)&Ah[m][kb] = uh;
                *(uint2*)&Al[m][kb] = ul;
            }
        }
        __syncthreads();

        // ---- compute: two k16 sub-steps ----
        #pragma unroll
        for (int kk = 0; kk < 32; kk += 16) {
            unsigned ah[2][4], al[2][4];
            #pragma unroll
            for (int mi = 0; mi < 2; mi++) {
                int row = warpm * 32 + mi * 16 + g;
                ah[mi][0] = *(const unsigned*)&Ah[row    ][kk + 2 * t4];
                ah[mi][1] = *(const unsigned*)&Ah[row + 8][kk + 2 * t4];
                ah[mi][2] = *(const unsigned*)&Ah[row    ][kk + 2 * t4 + 8];
                ah[mi][3] = *(const unsigned*)&Ah[row + 8][kk + 2 * t4 + 8];
                al[mi][0] = *(const unsigned*)&Al[row    ][kk + 2 * t4];
                al[mi][1] = *(const unsigned*)&Al[row + 8][kk + 2 * t4];
                al[mi][2] = *(const unsigned*)&Al[row    ][kk + 2 * t4 + 8];
                al[mi][3] = *(const unsigned*)&Al[row + 8][kk + 2 * t4 + 8];
            }
            unsigned bh[4][2], bl[4][2];
            #pragma unroll
            for (int ji = 0; ji < 4; ji++) {
                int j = warpj * 32 + ji * 8 + g;
                bh[ji][0] = *(const unsigned*)&Wh[j][kk + 2 * t4];
                bh[ji][1] = *(const unsigned*)&Wh[j][kk + 2 * t4 + 8];
                bl[ji][0] = *(const unsigned*)&Wl[j][kk + 2 * t4];
                bl[ji][1] = *(const unsigned*)&Wl[j][kk + 2 * t4 + 8];
            }
            #pragma unroll
            for (int mi = 0; mi < 2; mi++)
                #pragma unroll
                for (int ji = 0; ji < 4; ji++) {
                    mma16816(acc[mi][ji], ah[mi], bh[ji]);
                    mma16816(acc[mi][ji], ah[mi], bl[ji]);
                    mma16816(acc[mi][ji], al[mi], bh[ji]);
                }
        }
        __syncthreads();
    }

    // ---- epilogue ----
    #pragma unroll
    for (int ji = 0; ji < 4; ji++) {
        int jx = warpj * 32 + ji * 8 + 2 * t4;
        float b0 = bias ? bias[j0 + jx]     : 0.f;
        float b1 = bias ? bias[j0 + jx + 1] : 0.f;
        #pragma unroll
        for (int mi = 0; mi < 2; mi++) {
            int m = warpm * 32 + mi * 16 + g;
            Cb[(size_t)jx * 4096 + m]           = (acc[mi][ji][0] + b0) * scale;
            Cb[(size_t)(jx + 1) * 4096 + m]     = (acc[mi][ji][1] + b1) * scale;
            Cb[(size_t)jx * 4096 + m + 8]       = (acc[mi][ji][2] + b0) * scale;
            Cb[(size_t)(jx + 1) * 4096 + m + 8] = (acc[mi][ji][3] + b1) * scale;
        }
    }
}

// ---------------- softmax over hd=16 on K (in place) ----------------------
__global__ __launch_bounds__(256) void ksoftmax_kernel()
{
    int idx = blockIdx.x * 256 + threadIdx.x;
    int n  = idx & 4095;
    int hh = idx >> 12;
    int bb = hh >> 2, h = hh & 3;
    float* base = g_qkv + ((size_t)(bb * 192 + 64 + h * 16)) * 4096 + n;
    float v[16];
    float mx = -3.4e38f;
    #pragma unroll
    for (int d = 0; d < 16; d++) { v[d] = base[(size_t)d * 4096]; mx = fmaxf(mx, v[d]); }
    float ssum = 0.f;
    #pragma unroll
    for (int d = 0; d < 16; d++) { v[d] = __expf(v[d] - mx); ssum += v[d]; }
    float inv = 1.0f / ssum;
    #pragma unroll
    for (int d = 0; d < 16; d++) base[(size_t)d * 4096] = v[d] * inv;
}

// ---------------- column stats (max, sumexp) over n for Q -----------------
__global__ __launch_bounds__(256) void qstats_kernel()
{
    __shared__ float red[256];
    int col = blockIdx.x;
    int bb = col >> 6, j = col & 63;
    const float* base = g_qkv + ((size_t)(bb * 192 + j)) * 4096;
    int t = threadIdx.x;
    float v[16];
    float mx = -3.4e38f;
    #pragma unroll
    for (int i = 0; i < 16; i++) { v[i] = base[t + i * 256]; mx = fmaxf(mx, v[i]); }
    red[t] = mx; __syncthreads();
    for (int s2 = 128; s2 > 0; s2 >>= 1) {
        if (t < s2) red[t] = fmaxf(red[t], red[t + s2]);
        __syncthreads();
    }
    mx = red[0]; __syncthreads();
    float sum = 0.f;
    #pragma unroll
    for (int i = 0; i < 16; i++) sum += __expf(v[i] - mx);
    red[t] = sum; __syncthreads();
    for (int s2 = 128; s2 > 0; s2 >>= 1) {
        if (t < s2) red[t] += red[t + s2];
        __syncthreads();
    }
    if (t == 0) { g_M[col] = mx; g_Z[col] = red[0]; }
}

// ---------------- context: C[d,e] = sum_n key[n,d] v[n,e], / Z ------------
__global__ __launch_bounds__(256) void context_kernel()
{
    __shared__ float ks[16][128];
    __shared__ float vs[16][128];
    int bh = blockIdx.x;
    int bb = bh >> 2, h = bh & 3;
    const float* kb = g_qkv + ((size_t)(bb * 192 + 64  + h * 16)) * 4096;
    const float* vb = g_qkv + ((size_t)(bb * 192 + 128 + h * 16)) * 4096;
    int t = threadIdx.x;
    int d = t >> 4, e = t & 15;
    float acc = 0.f;
    for (int n0 = 0; n0 < 4096; n0 += 128) {
        #pragma unroll
        for (int i = 0; i < 2; i++) {
            int idx = t * 2 + i;
            int row = idx >> 5;
            int c4  = (idx & 31) * 4;
            *(float4*)&ks[row][c4] = *(const float4*)(kb + (size_t)row * 4096 + n0 + c4);
            *(float4*)&vs[row][c4] = *(const float4*)(vb + (size_t)row * 4096 + n0 + c4);
        }
        __syncthreads();
        #pragma unroll
        for (int q4 = 0; q4 < 32; q4++) {
            float4 a = *(const float4*)&ks[d][q4 * 4];
            float4 b = *(const float4*)&vs[e][q4 * 4];
            acc += a.x * b.x + a.y * b.y + a.z * b.z + a.w * b.w;
        }
        __syncthreads();
    }
    float z = g_Z[bb * 64 + h * 16 + d];
    g_ctx[(size_t)bh * 256 + d * 16 + e] = acc / z;
}

// ---------------- attn out: ao = exp(q-M) @ ctx, reference reshape folded:
//   pixel  n' = h*1024 + (n>>2),  chan c' = 16*(n&3) + e
__global__ __launch_bounds__(256) void attnout_kernel()
{
    __shared__ float cs[1024];
    __shared__ float ms[64];
    int bb = blockIdx.x >> 4;
    int nt = blockIdx.x & 15;
    int t  = threadIdx.x;
    int n  = nt * 256 + t;
    if (t < 64) ms[t] = g_M[bb * 64 + t];
    for (int i = t; i < 1024; i += 256) cs[i] = g_ctx[(size_t)bb * 1024 + i];
    __syncthreads();
    const float* qb = g_qkv + (size_t)bb * 192 * 4096 + n;
    int cbase = 16 * (n & 3);
    int pbase = n >> 2;
    for (int h = 0; h < 4; h++) {
        float acc[16];
        #pragma unroll
        for (int e = 0; e < 16; e++) acc[e] = 0.f;
        #pragma unroll
        for (int d = 0; d < 16; d++) {
            int jc = h * 16 + d;
            float qv = __expf(qb[(size_t)jc * 4096] - ms[jc]);
            const float4* crow = (const float4*)&cs[jc * 16];
            #pragma unroll
            for (int e4 = 0; e4 < 4; e4++) {
                float4 cv = crow[e4];
                acc[e4 * 4 + 0] += qv * cv.x;
                acc[e4 * 4 + 1] += qv * cv.y;
                acc[e4 * 4 + 2] += qv * cv.z;
                acc[e4 * 4 + 3] += qv * cv.w;
            }
        }
        int np = h * 1024 + pbase;
        #pragma unroll
        for (int e = 0; e < 16; e++)
            g_ao[((size_t)(bb * 64 + cbase + e)) * 4096 + np] = acc[e];
    }
}

// ---------------- launch ---------------------------------------------------
extern "C" void kernel_launch(void* const* d_in, const int* in_sizes, int n_in,
                              void* d_out, int out_size)
{
    const float* x   = (const float*)d_in[0];
    const float* w3  = (const float*)d_in[1];
    const float* b3  = (const float*)d_in[2];
    const float* w5  = (const float*)d_in[3];
    const float* b5  = (const float*)d_in[4];
    const float* w7  = (const float*)d_in[5];
    const float* b7  = (const float*)d_in[6];
    const float* w9  = (const float*)d_in[7];
    const float* b9  = (const float*)d_in[8];
    const float* w_qkv   = (const float*)d_in[9];
    const float* w_proj  = (const float*)d_in[10];
    const float* b_proj  = (const float*)d_in[11];
    const float* w_final = (const float*)d_in[12];
    const float* b_final = (const float*)d_in[13];
    const float* scale_w = (const float*)d_in[14];
    float* out = (float*)d_out;

    float *yp, *qkvp, *aop, *catp;
    cudaGetSymbolAddress((void**)&yp,   g_y);
    cudaGetSymbolAddress((void**)&qkvp, g_qkv);
    cudaGetSymbolAddress((void**)&aop,  g_ao);
    cudaGetSymbolAddress((void**)&catp, g_cat);

    // 1. depthwise conv + bias + residual + relu  -> g_y (bb,c,n)
    dwconv_kernel<<<NB * NDIM, 256>>>(x, w3, b3, w5, b5, w7, b7, w9, b9);

    // 2. QKV GEMM: (262144 x 64) @ (192 x 64)^T -> g_qkv
    gemm_tc<<<dim3(262144 / 128, 3), 256>>>(yp, w_qkv, nullptr, nullptr, qkvp,
                                            64, 64L * 4096, 192L * 4096);

    // 3. softmax over hd for K (in place)
    ksoftmax_kernel<<<4096, 256>>>();

    // 4. column stats for Q softmax (axis = n)
    qstats_kernel<<<4096, 256>>>();

    // 5. context = key^T v, folded / Z
    context_kernel<<<256, 256>>>();

    // 6. attention out -> g_ao (scrambled reshape layout)
    attnout_kernel<<<1024, 256>>>();

    // 7. proj GEMM + bias + branch scale -> g_cat
    gemm_tc<<<dim3(262144 / 128, 1), 256>>>(aop, w_proj, b_proj, scale_w, catp,
                                            64, 64L * 4096, 64L * 4096);

    // 8. final 1x1 conv -> d_out
    gemm_tc<<<dim3(65536 / 128, 4), 256>>>(catp, w_final, b_final, nullptr, out,
                                           256, 256L * 4096, 256L * 4096);
}